// round 4
// baseline (speedup 1.0000x reference)
#include <cuda_runtime.h>
#include <cuda_bf16.h>

typedef unsigned long long u64;

// ---------------------------------------------------------------------------
// Problem constants
// ---------------------------------------------------------------------------
#define ATTRC    16
#define RADIALC  8

// ---------------------------------------------------------------------------
// Packed f32x2 helpers (Blackwell): fma.rn.f32x2 on 64-bit register pairs.
// ---------------------------------------------------------------------------
__device__ __forceinline__ u64 fma2(u64 a, u64 b, u64 c) {
    u64 d;
    asm("fma.rn.f32x2 %0, %1, %2, %3;" : "=l"(d) : "l"(a), "l"(b), "l"(c));
    return d;
}
__device__ __forceinline__ u64 splat2(float w) {
    u64 d;
    unsigned int b = __float_as_uint(w);
    asm("mov.b64 %0, {%1, %1};" : "=l"(d) : "r"(b));
    return d;
}
__device__ __forceinline__ float2 unpk(u64 v) {
    unsigned int lo, hi;
    asm("mov.b64 {%0, %1}, %2;" : "=r"(lo), "=r"(hi) : "l"(v));
    return make_float2(__uint_as_float(lo), __uint_as_float(hi));
}

// ---------------------------------------------------------------------------
// Device scratch
// ---------------------------------------------------------------------------
__device__ __align__(16) float g_WE[32768];        // edge weights [k=(r*32+u)][wp][4 blocks]
__device__ __align__(16) float g_WS[32768];        // node weights [k2=(u*16+v)][wp][2 paths]
__device__ __align__(16) float g_M[10000 * 128];   // messages

// ---------------------------------------------------------------------------
// Fold kernels.  c_edge = (1/sqrt8)*(1/8)*(1/sqrt32) = 1/128
//                c_node = (1/sqrt512)*(1/sqrt32)     = 1/128
// ---------------------------------------------------------------------------
__global__ void fold_edge_kernel(const float* __restrict__ Wgen,
                                 const float* __restrict__ L1s,
                                 const float* __restrict__ L1v)
{
    int idx = blockIdx.x * blockDim.x + threadIdx.x;   // < 32768
    int b   = idx >> 13;            // 0..3 (A,B,C,D)
    int rem = idx & 8191;
    int r   = rem >> 10;            // 0..7
    int u   = (rem >> 5) & 31;
    int wp  = rem & 31;

    const float* wg = Wgen + r * 4096 + b * 1024 + u * 32;
    const float* L  = (b == 1 || b == 2) ? L1v : L1s;

    float acc = 0.f;
#pragma unroll
    for (int w = 0; w < 32; w++) acc = fmaf(wg[w], L[w * 32 + wp], acc);

    float c = 0.0078125f;                    // 1/128
    if (b == 3) c *= 0.57735026918962576f;   // fold 1/sqrt(3) of the dot into WD
    g_WE[(r * 32 + u) * 128 + wp * 4 + b] = acc * c;
}

__global__ void fold_node_kernel(const float* __restrict__ WS0,
                                 const float* __restrict__ WS1,
                                 const float* __restrict__ L2s,
                                 const float* __restrict__ L2v)
{
    int idx = blockIdx.x * blockDim.x + threadIdx.x;   // < 32768
    int sb  = idx >> 14;            // 0: scalar, 1: vector
    int rem = idx & 16383;
    int uv  = rem >> 5;             // u*16+v
    int wp  = rem & 31;

    const float* ws = (sb ? WS1 : WS0) + uv * 32;
    const float* L  = sb ? L2v : L2s;

    float acc = 0.f;
#pragma unroll
    for (int w = 0; w < 32; w++) acc = fmaf(ws[w], L[w * 32 + wp], acc);

    g_WS[uv * 64 + wp * 2 + sb] = acc * 0.0078125f;
}

__global__ void zero_m_kernel(int n)
{
    int i = blockIdx.x * blockDim.x + threadIdx.x;
    if (i < n) g_M[i] = 0.f;
}

// ---------------------------------------------------------------------------
// Edge kernel: 512 threads, persistent, 64-edge tiles.
// x arrays use row stride 68 floats (16B-aligned rows, 4-way staging conflicts).
// ---------------------------------------------------------------------------
#define XROW 68
#define XARR 2184
#define EW_OFF    0
#define EXS_OFF   32768
#define EXV_OFF(i) (EXS_OFF + XARR * (1 + (i)))
#define EDOT_OFF  (EXS_OFF + XARR * 4)            // 41504
#define EEF_OFF   (EXS_OFF + XARR * 5)            // 43688  [8][64]
#define EYS_OFF   (EEF_OFF + 512)                 // 44200  [64]
#define EYV_OFF   (EYS_OFF + 64)                  // 44264  [3][64]
#define ESND_OFF  (EYV_OFF + 192)                 // 44456  int[64]
#define ERCV_OFF  (ESND_OFF + 64)                 // 44520  int[64]
#define EDGE_SMEM_FLOATS (ERCV_OFF + 64)          // 44584
#define EDGE_SMEM_BYTES  (EDGE_SMEM_FLOATS * 4)

__global__ void __launch_bounds__(512, 1)
edge_kernel(const float* __restrict__ node_feats,
            const float* __restrict__ edge_attrs,
            const float* __restrict__ edge_feats,
            const int*   __restrict__ edge_index,
            int E)
{
    extern __shared__ float s[];
    const int tid  = threadIdx.x;
    const int lane = tid & 31;
    const int eo   = tid >> 5;     // warp 0..15
    const int eb   = eo << 2;      // 4 edges per warp

    // stage folded weights (128 KB) once per block
    for (int i = tid; i < 8192; i += 512)
        ((float4*)s)[i] = ((const float4*)g_WE)[i];

    int* sSnd = (int*)&s[ESND_OFF];
    int* sRcv = (int*)&s[ERCV_OFF];

    const int ntiles = (E + 63) >> 6;

    for (int t = blockIdx.x; t < ntiles; t += gridDim.x) {
        const int e0 = t << 6;
        __syncthreads();   // protect smem reuse across tiles (covers weights on 1st)

        // ---- indices + edge_attrs ----
        if (tid < 64) {
            int ge = e0 + tid;
            if (ge < E) {
                sSnd[tid] = edge_index[ge];
                sRcv[tid] = edge_index[E + ge];
                float4 ea = *(const float4*)&edge_attrs[(size_t)ge * 4];
                s[EYS_OFF + tid]       = ea.x;
                s[EYV_OFF + tid]       = ea.y;
                s[EYV_OFF + 64 + tid]  = ea.z;
                s[EYV_OFF + 128 + tid] = ea.w;
            } else {
                sSnd[tid] = 0; sRcv[tid] = -1;
                s[EYS_OFF + tid] = 0.f;
                s[EYV_OFF + tid] = 0.f; s[EYV_OFF + 64 + tid] = 0.f; s[EYV_OFF + 128 + tid] = 0.f;
            }
        }
        // ---- radial features ef[r][e] ----
        {
            int e = tid >> 3, r = tid & 7;
            int ge = e0 + e;
            s[EEF_OFF + r * 64 + e] = (ge < E) ? edge_feats[(size_t)ge * 8 + r] : 0.f;
        }
        __syncthreads();

        // ---- gather sender features (transposed into [f][e], stride 68) ----
        for (int q = tid; q < 64 * 128; q += 512) {
            int e = q >> 7, f = q & 127;
            float v = node_feats[(size_t)sSnd[e] * 128 + f];
            if (f < 32) {
                s[EXS_OFF + f * XROW + e] = v;
            } else {
                int tt = f - 32;
                int uu = tt / 3;
                int ii = tt - uu * 3;
                s[EXV_OFF(ii) + uu * XROW + e] = v;
            }
        }
        __syncthreads();

        // ---- dot[u][e] = xv . yv  (1/sqrt3 folded into WD) ----
        for (int q = tid; q < 2048; q += 512) {
            int u = q >> 6, e = q & 63;
            float d = s[EXV_OFF(0) + u * XROW + e] * s[EYV_OFF + e]
                    + s[EXV_OFF(1) + u * XROW + e] * s[EYV_OFF + 64 + e]
                    + s[EXV_OFF(2) + u * XROW + e] * s[EYV_OFF + 128 + e];
            s[EDOT_OFF + u * XROW + e] = d;
        }
        __syncthreads();

        // tot layout (pairs over edges): [0,1]=A [2,3]=B [4,5]=C0 [6,7]=C1 [8,9]=C2 [10,11]=D
        u64 tot[12];
#pragma unroll
        for (int v = 0; v < 12; v++) tot[v] = 0ull;

        const char* wbase  = (const char*)&s[EW_OFF + lane * 4];
        const char* xsB    = (const char*)&s[EXS_OFF    + eb];
        const char* xv0B   = (const char*)&s[EXV_OFF(0) + eb];
        const char* xv1B   = (const char*)&s[EXV_OFF(1) + eb];
        const char* xv2B   = (const char*)&s[EXV_OFF(2) + eb];
        const char* dotB   = (const char*)&s[EDOT_OFF   + eb];

#pragma unroll 1
        for (int r = 0; r < 8; r++) {
            u64 part[12];
#pragma unroll
            for (int v = 0; v < 12; v++) part[v] = 0ull;

            const char* wrow = wbase + (size_t)(r << 5) * 512;   // k*128 floats = 512 B

#pragma unroll
            for (int u = 0; u < 32; u++) {
                float4 wv = *(const float4*)(wrow + u * 512);
                u64 wa = splat2(wv.x), wb = splat2(wv.y),
                    wc = splat2(wv.z), wd = splat2(wv.w);

                ulonglong2 a0 = *(const ulonglong2*)(xsB  + u * (XROW * 4));
                ulonglong2 c0 = *(const ulonglong2*)(xv0B + u * (XROW * 4));
                ulonglong2 c1 = *(const ulonglong2*)(xv1B + u * (XROW * 4));
                ulonglong2 c2 = *(const ulonglong2*)(xv2B + u * (XROW * 4));
                ulonglong2 dd = *(const ulonglong2*)(dotB + u * (XROW * 4));

                part[0]  = fma2(a0.x, wa, part[0]);  part[1]  = fma2(a0.y, wa, part[1]);
                part[2]  = fma2(a0.x, wb, part[2]);  part[3]  = fma2(a0.y, wb, part[3]);
                part[4]  = fma2(c0.x, wc, part[4]);  part[5]  = fma2(c0.y, wc, part[5]);
                part[6]  = fma2(c1.x, wc, part[6]);  part[7]  = fma2(c1.y, wc, part[7]);
                part[8]  = fma2(c2.x, wc, part[8]);  part[9]  = fma2(c2.y, wc, part[9]);
                part[10] = fma2(dd.x, wd, part[10]); part[11] = fma2(dd.y, wd, part[11]);
            }

            // apply ef[r] to this r's partials
            ulonglong2 efp = *(const ulonglong2*)&s[EEF_OFF + (r << 6) + eb];
#pragma unroll
            for (int v = 0; v < 12; v += 2) {
                tot[v]     = fma2(efp.x, part[v],     tot[v]);
                tot[v + 1] = fma2(efp.y, part[v + 1], tot[v + 1]);
            }
        }

        // ---- epilogue + scatter-add ----
#pragma unroll
        for (int p = 0; p < 2; p++) {
            float2 A  = unpk(tot[0 + p]);
            float2 B  = unpk(tot[2 + p]);
            float2 C0 = unpk(tot[4 + p]);
            float2 C1 = unpk(tot[6 + p]);
            float2 C2 = unpk(tot[8 + p]);
            float2 D  = unpk(tot[10 + p]);
#pragma unroll
            for (int h = 0; h < 2; h++) {
                int e = eb + 2 * p + h;
                int recv = sRcv[e];
                if (recv < 0) continue;
                float a  = h ? A.y  : A.x;
                float b  = h ? B.y  : B.x;
                float c0 = h ? C0.y : C0.x;
                float c1 = h ? C1.y : C1.x;
                float c2 = h ? C2.y : C2.x;
                float d  = h ? D.y  : D.x;
                float ysv = s[EYS_OFF + e];
                float yv0 = s[EYV_OFF + e], yv1 = s[EYV_OFF + 64 + e], yv2 = s[EYV_OFF + 128 + e];
                float* dst = g_M + (size_t)recv * 128;
                atomicAdd(dst + lane,              fmaf(a, ysv, d));
                atomicAdd(dst + 32 + lane * 3 + 0, fmaf(b, yv0, c0 * ysv));
                atomicAdd(dst + 32 + lane * 3 + 1, fmaf(b, yv1, c1 * ysv));
                atomicAdd(dst + 32 + lane * 3 + 2, fmaf(b, yv2, c2 * ysv));
            }
        }
    }
}

// ---------------------------------------------------------------------------
// Node kernel: 512 threads, persistent, 64-node tiles.
//   out[w,e] = M[w,e] + sum_v na[v,e] * (sum_u WS[u,v,w] M[u,e])
// ---------------------------------------------------------------------------
#define NW_OFF    0
#define NMS_OFF   32768
#define NMV_OFF(i) (NMS_OFF + XARR * (1 + (i)))
#define NNA_OFF   (NMS_OFF + XARR * 4)            // 41504  [16][68]
#define NODE_SMEM_FLOATS (NNA_OFF + 16 * XROW)    // 42592
#define NODE_SMEM_BYTES  (NODE_SMEM_FLOATS * 4)

__global__ void __launch_bounds__(512, 1)
node_kernel(const float* __restrict__ node_attrs,
            float* __restrict__ out,
            int N)
{
    extern __shared__ float s[];
    const int tid  = threadIdx.x;
    const int lane = tid & 31;
    const int eo   = tid >> 5;
    const int eb   = eo << 2;

    for (int i = tid; i < 8192; i += 512)
        ((float4*)s)[i] = ((const float4*)g_WS)[i];

    const int ntiles = (N + 63) >> 6;

    for (int t = blockIdx.x; t < ntiles; t += gridDim.x) {
        const int n0 = t << 6;
        __syncthreads();

        // ---- stage Ms / Mv ----
        for (int q = tid; q < 64 * 128; q += 512) {
            int e = q >> 7, f = q & 127;
            int n = n0 + e;
            float v = (n < N) ? g_M[(size_t)n * 128 + f] : 0.f;
            if (f < 32) {
                s[NMS_OFF + f * XROW + e] = v;
            } else {
                int tt = f - 32;
                int uu = tt / 3;
                int ii = tt - uu * 3;
                s[NMV_OFF(ii) + uu * XROW + e] = v;
            }
        }
        // ---- stage node_attrs ----
        for (int q = tid; q < 64 * 16; q += 512) {
            int e = q >> 4, v = q & 15;
            int n = n0 + e;
            s[NNA_OFF + v * XROW + e] = (n < N) ? node_attrs[(size_t)n * 16 + v] : 0.f;
        }
        __syncthreads();

        // tot pairs: [0,1]=S [2,3]=V0 [4,5]=V1 [6,7]=V2
        u64 tot[8];
#pragma unroll
        for (int v = 0; v < 8; v++) tot[v] = 0ull;

        const char* msB  = (const char*)&s[NMS_OFF    + eb];
        const char* mv0B = (const char*)&s[NMV_OFF(0) + eb];
        const char* mv1B = (const char*)&s[NMV_OFF(1) + eb];
        const char* mv2B = (const char*)&s[NMV_OFF(2) + eb];

#pragma unroll 1
        for (int v = 0; v < 16; v++) {
            u64 part[8];
#pragma unroll
            for (int q = 0; q < 8; q++) part[q] = 0ull;

            const char* wrow = (const char*)&s[NW_OFF + v * 64 + lane * 2];

#pragma unroll
            for (int u = 0; u < 32; u++) {
                float2 wv = *(const float2*)(wrow + u * 4096);   // k2=(u*16+v), 64 floats apart in v, 1024 in u
                u64 w0 = splat2(wv.x), w1 = splat2(wv.y);

                ulonglong2 m0 = *(const ulonglong2*)(msB  + u * (XROW * 4));
                ulonglong2 m1 = *(const ulonglong2*)(mv0B + u * (XROW * 4));
                ulonglong2 m2 = *(const ulonglong2*)(mv1B + u * (XROW * 4));
                ulonglong2 m3 = *(const ulonglong2*)(mv2B + u * (XROW * 4));

                part[0] = fma2(m0.x, w0, part[0]); part[1] = fma2(m0.y, w0, part[1]);
                part[2] = fma2(m1.x, w1, part[2]); part[3] = fma2(m1.y, w1, part[3]);
                part[4] = fma2(m2.x, w1, part[4]); part[5] = fma2(m2.y, w1, part[5]);
                part[6] = fma2(m3.x, w1, part[6]); part[7] = fma2(m3.y, w1, part[7]);
            }

            ulonglong2 nap = *(const ulonglong2*)&s[NNA_OFF + v * XROW + eb];
#pragma unroll
            for (int q = 0; q < 8; q += 2) {
                tot[q]     = fma2(nap.x, part[q],     tot[q]);
                tot[q + 1] = fma2(nap.y, part[q + 1], tot[q + 1]);
            }
        }

        // ---- epilogue: out = M + skip ----
#pragma unroll
        for (int p = 0; p < 2; p++) {
            float2 S  = unpk(tot[0 + p]);
            float2 V0 = unpk(tot[2 + p]);
            float2 V1 = unpk(tot[4 + p]);
            float2 V2 = unpk(tot[6 + p]);
#pragma unroll
            for (int h = 0; h < 2; h++) {
                int e = eb + 2 * p + h;
                int n = n0 + e;
                if (n >= N) continue;
                float* o = out + (size_t)n * 128;
                o[lane]              = s[NMS_OFF    + lane * XROW + e] + (h ? S.y  : S.x);
                o[32 + lane * 3 + 0] = s[NMV_OFF(0) + lane * XROW + e] + (h ? V0.y : V0.x);
                o[32 + lane * 3 + 1] = s[NMV_OFF(1) + lane * XROW + e] + (h ? V1.y : V1.x);
                o[32 + lane * 3 + 2] = s[NMV_OFF(2) + lane * XROW + e] + (h ? V2.y : V2.x);
            }
        }
    }
}

// ---------------------------------------------------------------------------
// Launch
// ---------------------------------------------------------------------------
extern "C" void kernel_launch(void* const* d_in, const int* in_sizes, int n_in,
                              void* d_out, int out_size)
{
    const float* node_attrs = (const float*)d_in[0];
    const float* node_feats = (const float*)d_in[1];
    const float* edge_attrs = (const float*)d_in[2];
    const float* edge_feats = (const float*)d_in[3];
    const int*   edge_index = (const int*)  d_in[4];
    const float* Wgen       = (const float*)d_in[5];
    const float* L1s        = (const float*)d_in[6];
    const float* L1v        = (const float*)d_in[7];
    const float* WS0        = (const float*)d_in[8];
    const float* WS1        = (const float*)d_in[9];
    const float* L2s        = (const float*)d_in[10];
    const float* L2v        = (const float*)d_in[11];
    float* out = (float*)d_out;

    const int N = in_sizes[0] / ATTRC;        // 10000
    const int E = in_sizes[3] / RADIALC;      // 100000

    cudaFuncSetAttribute(edge_kernel, cudaFuncAttributeMaxDynamicSharedMemorySize, EDGE_SMEM_BYTES);
    cudaFuncSetAttribute(node_kernel, cudaFuncAttributeMaxDynamicSharedMemorySize, NODE_SMEM_BYTES);

    fold_edge_kernel<<<64, 512>>>(Wgen, L1s, L1v);
    fold_node_kernel<<<64, 512>>>(WS0, WS1, L2s, L2v);
    zero_m_kernel<<<(N * 128 + 511) / 512, 512>>>(N * 128);
    edge_kernel<<<148, 512, EDGE_SMEM_BYTES>>>(node_feats, edge_attrs, edge_feats, edge_index, E);
    node_kernel<<<148, 512, NODE_SMEM_BYTES>>>(node_attrs, out, N);
}

// round 5
// speedup vs baseline: 6.7138x; 6.7138x over previous
#include <cuda_runtime.h>
#include <cuda_bf16.h>

typedef unsigned long long u64;

#define ATTRC    16
#define RADIALC  8

// ---------------------------------------------------------------------------
// Packed f32x2 helpers (Blackwell)
// ---------------------------------------------------------------------------
__device__ __forceinline__ u64 fma2(u64 a, u64 b, u64 c) {
    u64 d;
    asm("fma.rn.f32x2 %0, %1, %2, %3;" : "=l"(d) : "l"(a), "l"(b), "l"(c));
    return d;
}
__device__ __forceinline__ u64 mul2(u64 a, u64 b) {
    u64 d;
    asm("mul.rn.f32x2 %0, %1, %2;" : "=l"(d) : "l"(a), "l"(b));
    return d;
}
__device__ __forceinline__ u64 splat2(float w) {
    u64 d;
    unsigned int b = __float_as_uint(w);
    asm("mov.b64 %0, {%1, %1};" : "=l"(d) : "r"(b));
    return d;
}
__device__ __forceinline__ float2 unpk(u64 v) {
    unsigned int lo, hi;
    asm("mov.b64 {%0, %1}, %2;" : "=r"(lo), "=r"(hi) : "l"(v));
    return make_float2(__uint_as_float(lo), __uint_as_float(hi));
}

// ---------------------------------------------------------------------------
// Device scratch
// ---------------------------------------------------------------------------
__device__ __align__(16) float g_WE[32768];        // [k=(r*32+u)][wp][4 blocks]
__device__ __align__(16) float g_WS[32768];        // [k2=(u*16+v)][wp][2 paths]
__device__ __align__(16) float g_M[10000 * 128];   // messages

// ---------------------------------------------------------------------------
// Fold kernels.  c_edge = (1/sqrt8)*(1/8)*(1/sqrt32) = 1/128
//                c_node = (1/sqrt512)*(1/sqrt32)     = 1/128
// ---------------------------------------------------------------------------
__global__ void fold_edge_kernel(const float* __restrict__ Wgen,
                                 const float* __restrict__ L1s,
                                 const float* __restrict__ L1v)
{
    int idx = blockIdx.x * blockDim.x + threadIdx.x;   // < 32768
    int b   = idx >> 13;
    int rem = idx & 8191;
    int r   = rem >> 10;
    int u   = (rem >> 5) & 31;
    int wp  = rem & 31;

    const float* wg = Wgen + r * 4096 + b * 1024 + u * 32;
    const float* L  = (b == 1 || b == 2) ? L1v : L1s;

    float acc = 0.f;
#pragma unroll
    for (int w = 0; w < 32; w++) acc = fmaf(wg[w], L[w * 32 + wp], acc);

    float c = 0.0078125f;
    if (b == 3) c *= 0.57735026918962576f;   // fold 1/sqrt(3) of the dot into WD
    g_WE[(r * 32 + u) * 128 + wp * 4 + b] = acc * c;
}

__global__ void fold_node_kernel(const float* __restrict__ WS0,
                                 const float* __restrict__ WS1,
                                 const float* __restrict__ L2s,
                                 const float* __restrict__ L2v)
{
    int idx = blockIdx.x * blockDim.x + threadIdx.x;   // < 32768
    int sb  = idx >> 14;
    int rem = idx & 16383;
    int uv  = rem >> 5;
    int wp  = rem & 31;

    const float* ws = (sb ? WS1 : WS0) + uv * 32;
    const float* L  = sb ? L2v : L2s;

    float acc = 0.f;
#pragma unroll
    for (int w = 0; w < 32; w++) acc = fmaf(ws[w], L[w * 32 + wp], acc);

    g_WS[uv * 64 + wp * 2 + sb] = acc * 0.0078125f;
}

__global__ void zero_m_kernel(int n)
{
    int i = blockIdx.x * blockDim.x + threadIdx.x;
    if (i < n) g_M[i] = 0.f;
}

// ---------------------------------------------------------------------------
// Edge kernel: 512 threads, persistent, 64-edge tiles.
// Staged arrays use row stride 68 floats (16B-aligned rows, limits conflicts).
// ---------------------------------------------------------------------------
#define XROW 68
#define XARR 2176
#define EW_OFF    0                                  // 32768
#define EXS_OFF   32768
#define EXV_OFF(i) (EXS_OFF + XARR * (1 + (i)))
#define EDOT_OFF  (EXS_OFF + XARR * 4)               // 41472
#define EA_OFF(v) (43648 + XARR * (v))               // 5 staged a-arrays, end 54528
#define EEF_OFF   54528                              // [8][64]
#define EYS_OFF   55040                              // [64]
#define EYV_OFF   55104                              // [3][64]
#define ESND_OFF  55296                              // int[64]
#define ERCV_OFF  55360                              // int[64]
#define EDGE_SMEM_FLOATS 55424
#define EDGE_SMEM_BYTES  (EDGE_SMEM_FLOATS * 4)      // 221696 B

__global__ void __launch_bounds__(512, 1)
edge_kernel(const float* __restrict__ node_feats,
            const float* __restrict__ edge_attrs,
            const float* __restrict__ edge_feats,
            const int*   __restrict__ edge_index,
            int E)
{
    extern __shared__ float s[];
    const int tid  = threadIdx.x;
    const int lane = tid & 31;
    const int eo   = tid >> 5;     // warp 0..15
    const int eb   = eo << 2;      // 4 edges per warp

    for (int i = tid; i < 8192; i += 512)
        ((float4*)s)[i] = ((const float4*)g_WE)[i];

    int* sSnd = (int*)&s[ESND_OFF];
    int* sRcv = (int*)&s[ERCV_OFF];

    const int ntiles = (E + 63) >> 6;

    for (int t = blockIdx.x; t < ntiles; t += gridDim.x) {
        const int e0 = t << 6;
        __syncthreads();   // protect smem reuse across tiles

        if (tid < 64) {
            int ge = e0 + tid;
            if (ge < E) {
                sSnd[tid] = edge_index[ge];
                sRcv[tid] = edge_index[E + ge];
                float4 ea = *(const float4*)&edge_attrs[(size_t)ge * 4];
                s[EYS_OFF + tid]       = ea.x;
                s[EYV_OFF + tid]       = ea.y;
                s[EYV_OFF + 64 + tid]  = ea.z;
                s[EYV_OFF + 128 + tid] = ea.w;
            } else {
                sSnd[tid] = 0; sRcv[tid] = -1;
                s[EYS_OFF + tid] = 0.f;
                s[EYV_OFF + tid] = 0.f; s[EYV_OFF + 64 + tid] = 0.f; s[EYV_OFF + 128 + tid] = 0.f;
            }
        }
        {
            int e = tid >> 3, r = tid & 7;
            int ge = e0 + e;
            s[EEF_OFF + r * 64 + e] = (ge < E) ? edge_feats[(size_t)ge * 8 + r] : 0.f;
        }
        __syncthreads();

        // ---- gather sender features (coalesced gmem; transposed to [f][e]) ----
        for (int q = tid; q < 64 * 128; q += 512) {
            int e = q >> 7, f = q & 127;
            float v = node_feats[(size_t)sSnd[e] * 128 + f];
            if (f < 32) {
                s[EXS_OFF + f * XROW + e] = v;
            } else {
                int tt = f - 32;
                int uu = tt / 3;
                int ii = tt - uu * 3;
                s[EXV_OFF(ii) + uu * XROW + e] = v;
            }
        }
        __syncthreads();

        // ---- dot[u][e] = xv . yv (1/sqrt3 folded into WD) ----
        for (int q = tid; q < 2048; q += 512) {
            int u = q >> 6, e = q & 63;
            float d = s[EXV_OFF(0) + u * XROW + e] * s[EYV_OFF + e]
                    + s[EXV_OFF(1) + u * XROW + e] * s[EYV_OFF + 64 + e]
                    + s[EXV_OFF(2) + u * XROW + e] * s[EYV_OFF + 128 + e];
            s[EDOT_OFF + u * XROW + e] = d;
        }

        // acc layout: [out*2 + pair]; outs: 0=A 1=B 2=C0 3=C1 4=C2 5=D
        u64 acc[12];
#pragma unroll
        for (int v = 0; v < 12; v++) acc[v] = 0ull;

#pragma unroll 1
        for (int r = 0; r < 8; r++) {
            __syncthreads();
            // ---- stage a[var][u][e] = ef[r][e] * x[var][u][e]  (f32x2) ----
#pragma unroll
            for (int j = 0; j < 10; j++) {
                int pp  = tid + j * 512;          // < 5120
                int var = pp >> 10;
                int rem = pp & 1023;
                int uu  = rem >> 5;
                int ep  = rem & 31;
                int xo  = uu * XROW + 2 * ep;
                u64 xv  = *(const u64*)&s[EXS_OFF + var * XARR + xo];   // var 0..4 covers xs,xv0..2,dot
                u64 efv = *(const u64*)&s[EEF_OFF + r * 64 + 2 * ep];
                *(u64*)&s[EA_OFF(var) + xo] = mul2(xv, efv);
            }
            __syncthreads();

            const int wbase = (r << 5) * 128 + lane * 4;
#pragma unroll 4
            for (int u = 0; u < 32; u++) {
                float4 wv = *(const float4*)&s[EW_OFF + wbase + u * 128];
                u64 wa = splat2(wv.x), wb = splat2(wv.y),
                    wc = splat2(wv.z), wd = splat2(wv.w);
                int ao = u * XROW + eb;
                ulonglong2 a0 = *(const ulonglong2*)&s[EA_OFF(0) + ao];
                ulonglong2 c0 = *(const ulonglong2*)&s[EA_OFF(1) + ao];
                ulonglong2 c1 = *(const ulonglong2*)&s[EA_OFF(2) + ao];
                ulonglong2 c2 = *(const ulonglong2*)&s[EA_OFF(3) + ao];
                ulonglong2 dd = *(const ulonglong2*)&s[EA_OFF(4) + ao];

                acc[0]  = fma2(a0.x, wa, acc[0]);  acc[1]  = fma2(a0.y, wa, acc[1]);
                acc[2]  = fma2(a0.x, wb, acc[2]);  acc[3]  = fma2(a0.y, wb, acc[3]);
                acc[4]  = fma2(c0.x, wc, acc[4]);  acc[5]  = fma2(c0.y, wc, acc[5]);
                acc[6]  = fma2(c1.x, wc, acc[6]);  acc[7]  = fma2(c1.y, wc, acc[7]);
                acc[8]  = fma2(c2.x, wc, acc[8]);  acc[9]  = fma2(c2.y, wc, acc[9]);
                acc[10] = fma2(dd.x, wd, acc[10]); acc[11] = fma2(dd.y, wd, acc[11]);
            }
        }

        // ---- epilogue + scatter-add ----
#pragma unroll
        for (int p = 0; p < 2; p++) {
            float2 A  = unpk(acc[0 + p]);
            float2 B  = unpk(acc[2 + p]);
            float2 C0 = unpk(acc[4 + p]);
            float2 C1 = unpk(acc[6 + p]);
            float2 C2 = unpk(acc[8 + p]);
            float2 D  = unpk(acc[10 + p]);
#pragma unroll
            for (int h = 0; h < 2; h++) {
                int e = eb + 2 * p + h;
                int recv = sRcv[e];
                if (recv < 0) continue;
                float a  = h ? A.y  : A.x;
                float b  = h ? B.y  : B.x;
                float c0 = h ? C0.y : C0.x;
                float c1 = h ? C1.y : C1.x;
                float c2 = h ? C2.y : C2.x;
                float d  = h ? D.y  : D.x;
                float ysv = s[EYS_OFF + e];
                float yv0 = s[EYV_OFF + e], yv1 = s[EYV_OFF + 64 + e], yv2 = s[EYV_OFF + 128 + e];
                float* dst = g_M + (size_t)recv * 128;
                atomicAdd(dst + lane,              fmaf(a, ysv, d));
                atomicAdd(dst + 32 + lane * 3 + 0, fmaf(b, yv0, c0 * ysv));
                atomicAdd(dst + 32 + lane * 3 + 1, fmaf(b, yv1, c1 * ysv));
                atomicAdd(dst + 32 + lane * 3 + 2, fmaf(b, yv2, c2 * ysv));
            }
        }
    }
}

// ---------------------------------------------------------------------------
// Node kernel: 512 threads, persistent, 64-node tiles, v-outer staging.
//   out[w,e] = M[w,e] + sum_v sum_u WS[u,v,w] * (na[v,e]*M[u,e])
// ---------------------------------------------------------------------------
#define NW_OFF    0                                  // 32768
#define NMS_OFF   32768
#define NMV_OFF(i) (NMS_OFF + XARR * (1 + (i)))
#define NNA_OFF   (NMS_OFF + XARR * 4)               // 41472 [16][68]
#define NC_OFF(v) (42560 + XARR * (v))               // 4 staged c-arrays, end 51264
#define NODE_SMEM_FLOATS 51264
#define NODE_SMEM_BYTES  (NODE_SMEM_FLOATS * 4)      // 205056 B

__global__ void __launch_bounds__(512, 1)
node_kernel(const float* __restrict__ node_attrs,
            float* __restrict__ out,
            int N)
{
    extern __shared__ float s[];
    const int tid  = threadIdx.x;
    const int lane = tid & 31;
    const int eo   = tid >> 5;
    const int eb   = eo << 2;

    for (int i = tid; i < 8192; i += 512)
        ((float4*)s)[i] = ((const float4*)g_WS)[i];

    const int ntiles = (N + 63) >> 6;

    for (int t = blockIdx.x; t < ntiles; t += gridDim.x) {
        const int n0 = t << 6;
        __syncthreads();

        for (int q = tid; q < 64 * 128; q += 512) {
            int e = q >> 7, f = q & 127;
            int n = n0 + e;
            float v = (n < N) ? g_M[(size_t)n * 128 + f] : 0.f;
            if (f < 32) {
                s[NMS_OFF + f * XROW + e] = v;
            } else {
                int tt = f - 32;
                int uu = tt / 3;
                int ii = tt - uu * 3;
                s[NMV_OFF(ii) + uu * XROW + e] = v;
            }
        }
        for (int q = tid; q < 64 * 16; q += 512) {
            int e = q >> 4, v = q & 15;
            int n = n0 + e;
            s[NNA_OFF + v * XROW + e] = (n < N) ? node_attrs[(size_t)n * 16 + v] : 0.f;
        }

        // acc pairs: [0,1]=S [2,3]=V0 [4,5]=V1 [6,7]=V2
        u64 acc[8];
#pragma unroll
        for (int q = 0; q < 8; q++) acc[q] = 0ull;

#pragma unroll 1
        for (int v = 0; v < 16; v++) {
            __syncthreads();
            // ---- stage c[var][u][e] = na[v][e] * M[var][u][e] ----
#pragma unroll
            for (int j = 0; j < 8; j++) {
                int pp  = tid + j * 512;          // < 4096
                int var = pp >> 10;
                int rem = pp & 1023;
                int uu  = rem >> 5;
                int ep  = rem & 31;
                int xo  = uu * XROW + 2 * ep;
                u64 mv  = *(const u64*)&s[NMS_OFF + var * XARR + xo];
                u64 nav = *(const u64*)&s[NNA_OFF + v * XROW + 2 * ep];
                *(u64*)&s[NC_OFF(var) + xo] = mul2(mv, nav);
            }
            __syncthreads();

            const int wbase = v * 64 + lane * 2;
#pragma unroll 4
            for (int u = 0; u < 32; u++) {
                float2 wv = *(const float2*)&s[NW_OFF + wbase + u * 1024];
                u64 w0 = splat2(wv.x), w1 = splat2(wv.y);
                int ao = u * XROW + eb;
                ulonglong2 m0 = *(const ulonglong2*)&s[NC_OFF(0) + ao];
                ulonglong2 m1 = *(const ulonglong2*)&s[NC_OFF(1) + ao];
                ulonglong2 m2 = *(const ulonglong2*)&s[NC_OFF(2) + ao];
                ulonglong2 m3 = *(const ulonglong2*)&s[NC_OFF(3) + ao];

                acc[0] = fma2(m0.x, w0, acc[0]); acc[1] = fma2(m0.y, w0, acc[1]);
                acc[2] = fma2(m1.x, w1, acc[2]); acc[3] = fma2(m1.y, w1, acc[3]);
                acc[4] = fma2(m2.x, w1, acc[4]); acc[5] = fma2(m2.y, w1, acc[5]);
                acc[6] = fma2(m3.x, w1, acc[6]); acc[7] = fma2(m3.y, w1, acc[7]);
            }
        }

        // ---- epilogue: out = M + skip ----
#pragma unroll
        for (int p = 0; p < 2; p++) {
            float2 S  = unpk(acc[0 + p]);
            float2 V0 = unpk(acc[2 + p]);
            float2 V1 = unpk(acc[4 + p]);
            float2 V2 = unpk(acc[6 + p]);
#pragma unroll
            for (int h = 0; h < 2; h++) {
                int e = eb + 2 * p + h;
                int n = n0 + e;
                if (n >= N) continue;
                float* o = out + (size_t)n * 128;
                o[lane]              = s[NMS_OFF    + lane * XROW + e] + (h ? S.y  : S.x);
                o[32 + lane * 3 + 0] = s[NMV_OFF(0) + lane * XROW + e] + (h ? V0.y : V0.x);
                o[32 + lane * 3 + 1] = s[NMV_OFF(1) + lane * XROW + e] + (h ? V1.y : V1.x);
                o[32 + lane * 3 + 2] = s[NMV_OFF(2) + lane * XROW + e] + (h ? V2.y : V2.x);
            }
        }
    }
}

// ---------------------------------------------------------------------------
// Launch
// ---------------------------------------------------------------------------
extern "C" void kernel_launch(void* const* d_in, const int* in_sizes, int n_in,
                              void* d_out, int out_size)
{
    const float* node_attrs = (const float*)d_in[0];
    const float* node_feats = (const float*)d_in[1];
    const float* edge_attrs = (const float*)d_in[2];
    const float* edge_feats = (const float*)d_in[3];
    const int*   edge_index = (const int*)  d_in[4];
    const float* Wgen       = (const float*)d_in[5];
    const float* L1s        = (const float*)d_in[6];
    const float* L1v        = (const float*)d_in[7];
    const float* WS0        = (const float*)d_in[8];
    const float* WS1        = (const float*)d_in[9];
    const float* L2s        = (const float*)d_in[10];
    const float* L2v        = (const float*)d_in[11];
    float* out = (float*)d_out;

    const int N = in_sizes[0] / ATTRC;        // 10000
    const int E = in_sizes[3] / RADIALC;      // 100000

    cudaFuncSetAttribute(edge_kernel, cudaFuncAttributeMaxDynamicSharedMemorySize, EDGE_SMEM_BYTES);
    cudaFuncSetAttribute(node_kernel, cudaFuncAttributeMaxDynamicSharedMemorySize, NODE_SMEM_BYTES);

    fold_edge_kernel<<<64, 512>>>(Wgen, L1s, L1v);
    fold_node_kernel<<<64, 512>>>(WS0, WS1, L2s, L2v);
    zero_m_kernel<<<(N * 128 + 511) / 512, 512>>>(N * 128);
    edge_kernel<<<148, 512, EDGE_SMEM_BYTES>>>(node_feats, edge_attrs, edge_feats, edge_index, E);
    node_kernel<<<148, 512, NODE_SMEM_BYTES>>>(node_attrs, out, N);
}